// round 11
// baseline (speedup 1.0000x reference)
#include <cuda_runtime.h>
#include <cstdint>

#define THREADS 128
#define NB 32
#define XS 68                    // smem row stride (floats): 272B, conflict-free LDSM phases
#define BUFF (NB * XS)           // floats per x ring buffer

__device__ __forceinline__ uint32_t smem_u32(const void* p) {
    uint32_t a;
    asm("{ .reg .u64 t; cvta.to.shared.u64 t, %1; cvt.u32.u64 %0, t; }" : "=r"(a) : "l"(p));
    return a;
}
__device__ __forceinline__ void ldsm_x4(uint32_t* r, uint32_t addr) {
    asm volatile("ldmatrix.sync.aligned.m8n8.x4.shared.b16 {%0,%1,%2,%3}, [%4];"
                 : "=r"(r[0]), "=r"(r[1]), "=r"(r[2]), "=r"(r[3]) : "r"(addr));
}
__device__ __forceinline__ void mma_tf32(float* d, const uint32_t* a, const uint32_t* b) {
    asm volatile("mma.sync.aligned.m16n8k8.row.col.f32.tf32.tf32.f32 "
                 "{%0,%1,%2,%3},{%4,%5,%6,%7},{%8,%9},{%0,%1,%2,%3};"
                 : "+f"(d[0]), "+f"(d[1]), "+f"(d[2]), "+f"(d[3])
                 : "r"(a[0]), "r"(a[1]), "r"(a[2]), "r"(a[3]), "r"(b[0]), "r"(b[1]));
}
__device__ __forceinline__ void cp16(uint32_t saddr, const void* gaddr) {
    asm volatile("cp.async.cg.shared.global [%0], [%1], 16;" :: "r"(saddr), "l"(gaddr));
}
__device__ __forceinline__ uint32_t to_tf32(float v) {
    uint32_t r;
    asm("cvt.rna.tf32.f32 %0, %1;" : "=r"(r) : "f"(v));
    return r;
}
__device__ __forceinline__ uint32_t to_tf32u(uint32_t v) {
    uint32_t r;
    asm("cvt.rna.tf32.f32 %0, %1;" : "=r"(r) : "f"(__uint_as_float(v)));
    return r;
}

// ---- single kernel: x (65536,25,64), weight (4,64,64) -> out (65536,35,64) ----
// out[n,m,:] = x[n,m+1,:] @ W[deg(m)] ; out[n,24:35,:] = 0
// All in-tensor offsets fit in 32 bits (out: 146.8M elems < 2^31).
__global__ __launch_bounds__(THREADS, 8)
void dwl_main(const float* __restrict__ x,
              const float* __restrict__ weight,
              float* __restrict__ out)
{
    extern __shared__ float xs[];
    const int t    = threadIdx.x;
    const int lane = t & 31;
    const int cw   = t >> 5;                 // col-warp: cols cw*16..cw*16+15

    // per-block base pointers (only 64-bit math done once)
    const float* xb   = x   + (unsigned)blockIdx.x * (NB * 1600u);
    float*       outb = out + (unsigned)blockIdx.x * (NB * 2240u);

    // zero-fill orders 24..34
    {
        const float4 z = make_float4(0.f, 0.f, 0.f, 0.f);
        for (int i = t; i < NB * 176; i += THREADS) {
            int r = i / 176;
            int j = i - r * 176;
            ((float4*)(outb + r * 2240 + 1536))[j] = z;
        }
    }

    const uint32_t xs_b = smem_u32(xs);

    // A-frag ldmatrix addressing (validated R5/R7-R10)
    const uint32_t a_row  = (uint32_t)(lane & 15);
    const uint32_t a_koff = (uint32_t)(lane >> 4) * 16;

    // stage x tile for order m into ring slot b (32 rows x 16 x 16B chunks)
    auto stage = [&](int m, int b) {
        const char* Xg = (const char*)(xb + (m + 1) * 64);
        uint32_t sb = xs_b + (uint32_t)b * (BUFF * 4);
        #pragma unroll
        for (int j = 0; j < 4; j++) {
            int i = t + THREADS * j;
            int r = i >> 4;
            int c = i & 15;
            cp16(sb + (uint32_t)(r * (XS * 4) + c * 16), Xg + r * 6400 + c * 16);
        }
        asm volatile("cp.async.commit_group;" ::: "memory");
    };

    // B fragments straight from weight (LDG, L2-hot, 4 sectors each) + RN round.
    // Per 8x8 tile: b0 k = lane&3, b1 k = (lane&3)+4; n = lane>>2.
    uint32_t bh[2][8][2];
    auto load_bfrags = [&](int deg) {
        const float* wb = weight + deg * 4096 + (lane & 3) * 64 + cw * 16 + (lane >> 2);
        #pragma unroll
        for (int nt = 0; nt < 2; nt++)
            #pragma unroll
            for (int ks = 0; ks < 8; ks++) {
                const float* p = wb + ks * 512 + nt * 8;
                bh[nt][ks][0] = to_tf32(p[0]);       // k = ks*8 + (lane&3)
                bh[nt][ks][1] = to_tf32(p[256]);     // k = ks*8 + (lane&3) + 4
            }
    };

    stage(0, 0);
    load_bfrags(0);

    for (int m = 0; m < 24; m++) {
        if (m < 23) {
            stage(m + 1, (m + 1) % 3);
            asm volatile("cp.async.wait_group 1;" ::: "memory");
        } else {
            asm volatile("cp.async.wait_group 0;" ::: "memory");
        }
        __syncthreads();

        if (m == 3)  load_bfrags(1);
        if (m == 8)  load_bfrags(2);
        if (m == 15) load_bfrags(3);

        const uint32_t abase0 = xs_b + (uint32_t)(m % 3) * (BUFF * 4)
                              + a_row * (XS * 4) + a_koff;

        #pragma unroll
        for (int mt = 0; mt < 2; mt++) {
            float acc0[4] = {0.f, 0.f, 0.f, 0.f};
            float acc1[4] = {0.f, 0.f, 0.f, 0.f};
            const uint32_t abase = abase0 + (uint32_t)(mt * 16 * XS * 4);
            #pragma unroll
            for (int ks = 0; ks < 8; ks++) {
                uint32_t a[4];
                ldsm_x4(a, abase + ks * 32);
                #pragma unroll
                for (int j = 0; j < 4; j++) a[j] = to_tf32u(a[j]);  // RN round A
                mma_tf32(acc0, a, bh[0][ks]);
                mma_tf32(acc1, a, bh[1][ks]);
            }
            const int row = mt * 16 + (lane >> 2);
            const int col = m * 64 + cw * 16 + (lane & 3) * 2;
            *(float2*)(outb + row * 2240 + col)           = make_float2(acc0[0], acc0[1]);
            *(float2*)(outb + (row + 8) * 2240 + col)     = make_float2(acc0[2], acc0[3]);
            *(float2*)(outb + row * 2240 + col + 8)       = make_float2(acc1[0], acc1[1]);
            *(float2*)(outb + (row + 8) * 2240 + col + 8) = make_float2(acc1[2], acc1[3]);
        }
        // ring depth 3: slot written in iter m was last read in iter m-2;
        // the barrier in iter m-1 orders those reads before these writes.
    }
}

extern "C" void kernel_launch(void* const* d_in, const int* in_sizes, int n_in,
                              void* d_out, int out_size)
{
    const float* x = (const float*)d_in[0];
    const float* w = (const float*)d_in[1];
    if (n_in >= 2 && in_sizes[0] < in_sizes[1]) {
        x = (const float*)d_in[1];
        w = (const float*)d_in[0];
    }
    float* out = (float*)d_out;

    const int smem_sz = 3 * BUFF * sizeof(float);   // 26112 B
    cudaFuncSetAttribute(dwl_main, cudaFuncAttributeMaxDynamicSharedMemorySize, smem_sz);
    dwl_main<<<65536 / NB, THREADS, smem_sz>>>(x, w, out);
}

// round 12
// speedup vs baseline: 1.0059x; 1.0059x over previous
#include <cuda_runtime.h>
#include <cstdint>

#define THREADS 128
#define NB 32
#define XS 68                    // smem row stride (floats): 272B, conflict-free LDSM phases
#define BUFF (NB * XS)           // floats per x ring buffer
#define DEPTH 4                  // ring depth (power of 2)

__device__ __forceinline__ uint32_t smem_u32(const void* p) {
    uint32_t a;
    asm("{ .reg .u64 t; cvta.to.shared.u64 t, %1; cvt.u32.u64 %0, t; }" : "=r"(a) : "l"(p));
    return a;
}
__device__ __forceinline__ void ldsm_x4(uint32_t* r, uint32_t addr) {
    asm volatile("ldmatrix.sync.aligned.m8n8.x4.shared.b16 {%0,%1,%2,%3}, [%4];"
                 : "=r"(r[0]), "=r"(r[1]), "=r"(r[2]), "=r"(r[3]) : "r"(addr));
}
__device__ __forceinline__ void mma_tf32(float* d, const uint32_t* a, const uint32_t* b) {
    asm volatile("mma.sync.aligned.m16n8k8.row.col.f32.tf32.tf32.f32 "
                 "{%0,%1,%2,%3},{%4,%5,%6,%7},{%8,%9},{%0,%1,%2,%3};"
                 : "+f"(d[0]), "+f"(d[1]), "+f"(d[2]), "+f"(d[3])
                 : "r"(a[0]), "r"(a[1]), "r"(a[2]), "r"(a[3]), "r"(b[0]), "r"(b[1]));
}
__device__ __forceinline__ void cp16(uint32_t saddr, const void* gaddr) {
    asm volatile("cp.async.cg.shared.global [%0], [%1], 16;" :: "r"(saddr), "l"(gaddr));
}
__device__ __forceinline__ uint32_t to_tf32(float v) {
    uint32_t r;
    asm("cvt.rna.tf32.f32 %0, %1;" : "=r"(r) : "f"(v));
    return r;
}
__device__ __forceinline__ uint32_t to_tf32u(uint32_t v) {
    uint32_t r;
    asm("cvt.rna.tf32.f32 %0, %1;" : "=r"(r) : "f"(__uint_as_float(v)));
    return r;
}

// ---- single kernel: x (65536,25,64), weight (4,64,64) -> out (65536,35,64) ----
// out[n,m,:] = x[n,m+1,:] @ W[deg(m)] ; out[n,24:35,:] = 0
__global__ __launch_bounds__(THREADS, 6)
void dwl_main(const float* __restrict__ x,
              const float* __restrict__ weight,
              float* __restrict__ out)
{
    extern __shared__ float xs[];
    const int t    = threadIdx.x;
    const int lane = t & 31;
    const int cw   = t >> 5;                 // col-warp: cols cw*16..cw*16+15

    const float* xb   = x   + (unsigned)blockIdx.x * (NB * 1600u);
    float*       outb = out + (unsigned)blockIdx.x * (NB * 2240u);

    // zero-fill orders 24..34
    {
        const float4 z = make_float4(0.f, 0.f, 0.f, 0.f);
        for (int i = t; i < NB * 176; i += THREADS) {
            int r = i / 176;
            int j = i - r * 176;
            ((float4*)(outb + r * 2240 + 1536))[j] = z;
        }
    }

    const uint32_t xs_b = smem_u32(xs);

    // A-frag ldmatrix addressing (validated R5/R7-R10)
    const uint32_t a_row  = (uint32_t)(lane & 15);
    const uint32_t a_koff = (uint32_t)(lane >> 4) * 16;

    // stage x tile for order m into ring slot b (32 rows x 16 x 16B chunks)
    auto stage = [&](int m, int b) {
        const char* Xg = (const char*)(xb + (m + 1) * 64);
        uint32_t sb = xs_b + (uint32_t)b * (BUFF * 4);
        #pragma unroll
        for (int j = 0; j < 4; j++) {
            int i = t + THREADS * j;
            int r = i >> 4;
            int c = i & 15;
            cp16(sb + (uint32_t)(r * (XS * 4) + c * 16), Xg + r * 6400 + c * 16);
        }
        asm volatile("cp.async.commit_group;" ::: "memory");
    };

    // B fragments straight from weight (LDG, L2-hot) + RN tf32 round.
    // Per 8x8 tile: b0 k = lane&3, b1 k = (lane&3)+4; n = lane>>2.
    uint32_t bh[2][8][2];
    auto load_bfrags = [&](int deg) {
        const float* wb = weight + deg * 4096 + (lane & 3) * 64 + cw * 16 + (lane >> 2);
        #pragma unroll
        for (int nt = 0; nt < 2; nt++)
            #pragma unroll
            for (int ks = 0; ks < 8; ks++) {
                const float* p = wb + ks * 512 + nt * 8;
                bh[nt][ks][0] = to_tf32(p[0]);       // k = ks*8 + (lane&3)
                bh[nt][ks][1] = to_tf32(p[256]);     // k = ks*8 + (lane&3) + 4
            }
    };

    // prime: two tiles in flight
    stage(0, 0);
    stage(1, 1);
    load_bfrags(0);

    for (int m = 0; m < 24; m++) {
        // Barrier FIRST: all warps' reads of tile m-1 (and earlier) complete.
        // Then staging tile m+2 into slot (m+2)&3 == slot of tile m-2 is safe
        // (tile m-2 reads preceded the barrier in iter m-1).
        __syncthreads();

        if (m < 22) {
            stage(m + 2, (m + 2) & (DEPTH - 1));
            asm volatile("cp.async.wait_group 2;" ::: "memory");  // tiles <= m done
        } else if (m == 22) {
            asm volatile("cp.async.wait_group 1;" ::: "memory");
        } else {
            asm volatile("cp.async.wait_group 0;" ::: "memory");
        }
        __syncthreads();   // make all threads' cp.async data visible block-wide

        if (m == 3)  load_bfrags(1);
        if (m == 8)  load_bfrags(2);
        if (m == 15) load_bfrags(3);

        const uint32_t abase0 = xs_b + (uint32_t)(m & (DEPTH - 1)) * (BUFF * 4)
                              + a_row * (XS * 4) + a_koff;

        #pragma unroll
        for (int mt = 0; mt < 2; mt++) {
            float acc0[4] = {0.f, 0.f, 0.f, 0.f};
            float acc1[4] = {0.f, 0.f, 0.f, 0.f};
            const uint32_t abase = abase0 + (uint32_t)(mt * 16 * XS * 4);
            #pragma unroll
            for (int ks = 0; ks < 8; ks++) {
                uint32_t a[4];
                ldsm_x4(a, abase + ks * 32);
                #pragma unroll
                for (int j = 0; j < 4; j++) a[j] = to_tf32u(a[j]);  // RN round A
                mma_tf32(acc0, a, bh[0][ks]);
                mma_tf32(acc1, a, bh[1][ks]);
            }
            const int row = mt * 16 + (lane >> 2);
            const int col = m * 64 + cw * 16 + (lane & 3) * 2;
            *(float2*)(outb + row * 2240 + col)           = make_float2(acc0[0], acc0[1]);
            *(float2*)(outb + (row + 8) * 2240 + col)     = make_float2(acc0[2], acc0[3]);
            *(float2*)(outb + row * 2240 + col + 8)       = make_float2(acc1[0], acc1[1]);
            *(float2*)(outb + (row + 8) * 2240 + col + 8) = make_float2(acc1[2], acc1[3]);
        }
    }
}

extern "C" void kernel_launch(void* const* d_in, const int* in_sizes, int n_in,
                              void* d_out, int out_size)
{
    const float* x = (const float*)d_in[0];
    const float* w = (const float*)d_in[1];
    if (n_in >= 2 && in_sizes[0] < in_sizes[1]) {
        x = (const float*)d_in[1];
        w = (const float*)d_in[0];
    }
    float* out = (float*)d_out;

    const int smem_sz = DEPTH * BUFF * sizeof(float);   // 34816 B
    cudaFuncSetAttribute(dwl_main, cudaFuncAttributeMaxDynamicSharedMemorySize, smem_sz);
    dwl_main<<<65536 / NB, THREADS, smem_sz>>>(x, w, out);
}

// round 13
// speedup vs baseline: 1.0863x; 1.0799x over previous
#include <cuda_runtime.h>
#include <cstdint>

#define THREADS 128
#define NB 32
#define XS 68                    // smem row stride (floats): 272B, conflict-free LDSM phases
#define BUFF (NB * XS)           // floats per x ring buffer

__device__ __forceinline__ uint32_t smem_u32(const void* p) {
    uint32_t a;
    asm("{ .reg .u64 t; cvta.to.shared.u64 t, %1; cvt.u32.u64 %0, t; }" : "=r"(a) : "l"(p));
    return a;
}
__device__ __forceinline__ void ldsm_x4(uint32_t* r, uint32_t addr) {
    asm volatile("ldmatrix.sync.aligned.m8n8.x4.shared.b16 {%0,%1,%2,%3}, [%4];"
                 : "=r"(r[0]), "=r"(r[1]), "=r"(r[2]), "=r"(r[3]) : "r"(addr));
}
__device__ __forceinline__ void mma_tf32(float* d, const uint32_t* a, const uint32_t* b) {
    asm volatile("mma.sync.aligned.m16n8k8.row.col.f32.tf32.tf32.f32 "
                 "{%0,%1,%2,%3},{%4,%5,%6,%7},{%8,%9},{%0,%1,%2,%3};"
                 : "+f"(d[0]), "+f"(d[1]), "+f"(d[2]), "+f"(d[3])
                 : "r"(a[0]), "r"(a[1]), "r"(a[2]), "r"(a[3]), "r"(b[0]), "r"(b[1]));
}
__device__ __forceinline__ void cp16(uint32_t saddr, const void* gaddr) {
    asm volatile("cp.async.cg.shared.global [%0], [%1], 16;" :: "r"(saddr), "l"(gaddr));
}
__device__ __forceinline__ uint32_t to_tf32(float v) {
    uint32_t r;
    asm("cvt.rna.tf32.f32 %0, %1;" : "=r"(r) : "f"(v));
    return r;
}
__device__ __forceinline__ uint32_t to_tf32u(uint32_t v) {
    uint32_t r;
    asm("cvt.rna.tf32.f32 %0, %1;" : "=r"(r) : "f"(__uint_as_float(v)));
    return r;
}
// streaming stores (evict-first): output has zero reuse; keep it out of L2
__device__ __forceinline__ void stcs2(float* p, float a, float b) {
    asm volatile("st.global.cs.v2.f32 [%0], {%1, %2};" :: "l"(p), "f"(a), "f"(b) : "memory");
}
__device__ __forceinline__ void stcs4z(float* p) {
    asm volatile("st.global.cs.v4.f32 [%0], {%1, %1, %1, %1};" :: "l"(p), "f"(0.f) : "memory");
}

// ---- single kernel: x (65536,25,64), weight (4,64,64) -> out (65536,35,64) ----
// out[n,m,:] = x[n,m+1,:] @ W[deg(m)] ; out[n,24:35,:] = 0
__global__ __launch_bounds__(THREADS, 7)
void dwl_main(const float* __restrict__ x,
              const float* __restrict__ weight,
              float* __restrict__ out)
{
    extern __shared__ float xs[];
    const int t    = threadIdx.x;
    const int lane = t & 31;
    const int cw   = t >> 5;                 // col-warp: cols cw*16..cw*16+15

    const float* xb   = x   + (unsigned)blockIdx.x * (NB * 1600u);
    float*       outb = out + (unsigned)blockIdx.x * (NB * 2240u);

    // zero-fill orders 24..34 (streaming stores)
    for (int i = t; i < NB * 176; i += THREADS) {
        int r = i / 176;
        int j = i - r * 176;
        stcs4z(outb + r * 2240 + 1536 + j * 4);
    }

    const uint32_t xs_b = smem_u32(xs);

    // A-frag ldmatrix addressing (validated R5/R7-R12)
    const uint32_t a_row  = (uint32_t)(lane & 15);
    const uint32_t a_koff = (uint32_t)(lane >> 4) * 16;

    // stage x tile for order m into ring slot b (32 rows x 16 x 16B chunks)
    auto stage = [&](int m, int b) {
        const char* Xg = (const char*)(xb + (m + 1) * 64);
        uint32_t sb = xs_b + (uint32_t)b * (BUFF * 4);
        #pragma unroll
        for (int j = 0; j < 4; j++) {
            int i = t + THREADS * j;
            int r = i >> 4;
            int c = i & 15;
            cp16(sb + (uint32_t)(r * (XS * 4) + c * 16), Xg + r * 6400 + c * 16);
        }
        asm volatile("cp.async.commit_group;" ::: "memory");
    };

    // B fragments straight from weight (LDG, L2-hot) + RN tf32 round.
    // Per 8x8 tile: b0 k = lane&3, b1 k = (lane&3)+4; n = lane>>2.
    uint32_t bh[2][8][2];
    auto load_bfrags = [&](int deg) {
        const float* wb = weight + deg * 4096 + (lane & 3) * 64 + cw * 16 + (lane >> 2);
        #pragma unroll
        for (int nt = 0; nt < 2; nt++)
            #pragma unroll
            for (int ks = 0; ks < 8; ks++) {
                const float* p = wb + ks * 512 + nt * 8;
                bh[nt][ks][0] = to_tf32(p[0]);       // k = ks*8 + (lane&3)
                bh[nt][ks][1] = to_tf32(p[256]);     // k = ks*8 + (lane&3) + 4
            }
    };

    stage(0, 0);
    load_bfrags(0);

    for (int m = 0; m < 24; m++) {
        if (m < 23) {
            stage(m + 1, (m + 1) % 3);
            asm volatile("cp.async.wait_group 1;" ::: "memory");
        } else {
            asm volatile("cp.async.wait_group 0;" ::: "memory");
        }
        __syncthreads();

        if (m == 3)  load_bfrags(1);
        if (m == 8)  load_bfrags(2);
        if (m == 15) load_bfrags(3);

        const uint32_t abase0 = xs_b + (uint32_t)(m % 3) * (BUFF * 4)
                              + a_row * (XS * 4) + a_koff;

        #pragma unroll
        for (int mt = 0; mt < 2; mt++) {
            float acc0[4] = {0.f, 0.f, 0.f, 0.f};
            float acc1[4] = {0.f, 0.f, 0.f, 0.f};
            const uint32_t abase = abase0 + (uint32_t)(mt * 16 * XS * 4);
            #pragma unroll
            for (int ks = 0; ks < 8; ks++) {
                uint32_t a[4];
                ldsm_x4(a, abase + ks * 32);
                #pragma unroll
                for (int j = 0; j < 4; j++) a[j] = to_tf32u(a[j]);  // RN round A
                mma_tf32(acc0, a, bh[0][ks]);
                mma_tf32(acc1, a, bh[1][ks]);
            }
            const int row = mt * 16 + (lane >> 2);
            const int col = m * 64 + cw * 16 + (lane & 3) * 2;
            stcs2(outb + row * 2240 + col,           acc0[0], acc0[1]);
            stcs2(outb + (row + 8) * 2240 + col,     acc0[2], acc0[3]);
            stcs2(outb + row * 2240 + col + 8,       acc1[0], acc1[1]);
            stcs2(outb + (row + 8) * 2240 + col + 8, acc1[2], acc1[3]);
        }
        // ring depth 3: slot written in iter m was last read in iter m-2;
        // the barrier in iter m-1 orders those reads before these writes.
    }
}

extern "C" void kernel_launch(void* const* d_in, const int* in_sizes, int n_in,
                              void* d_out, int out_size)
{
    const float* x = (const float*)d_in[0];
    const float* w = (const float*)d_in[1];
    if (n_in >= 2 && in_sizes[0] < in_sizes[1]) {
        x = (const float*)d_in[1];
        w = (const float*)d_in[0];
    }
    float* out = (float*)d_out;

    const int smem_sz = 3 * BUFF * sizeof(float);   // 26112 B
    cudaFuncSetAttribute(dwl_main, cudaFuncAttributeMaxDynamicSharedMemorySize, smem_sz);
    dwl_main<<<65536 / NB, THREADS, smem_sz>>>(x, w, out);
}

// round 14
// speedup vs baseline: 1.0943x; 1.0074x over previous
#include <cuda_runtime.h>
#include <cstdint>

#define THREADS 128
#define NB 32
#define XS 68                    // smem row stride (floats): 272B, conflict-free LDSM phases
#define BUFF (NB * XS)           // floats per x ring buffer

__device__ __forceinline__ uint32_t smem_u32(const void* p) {
    uint32_t a;
    asm("{ .reg .u64 t; cvta.to.shared.u64 t, %1; cvt.u32.u64 %0, t; }" : "=r"(a) : "l"(p));
    return a;
}
__device__ __forceinline__ void ldsm_x4(uint32_t* r, uint32_t addr) {
    asm volatile("ldmatrix.sync.aligned.m8n8.x4.shared.b16 {%0,%1,%2,%3}, [%4];"
                 : "=r"(r[0]), "=r"(r[1]), "=r"(r[2]), "=r"(r[3]) : "r"(addr));
}
__device__ __forceinline__ void mma_tf32(float* d, const uint32_t* a, const uint32_t* b) {
    asm volatile("mma.sync.aligned.m16n8k8.row.col.f32.tf32.tf32.f32 "
                 "{%0,%1,%2,%3},{%4,%5,%6,%7},{%8,%9},{%0,%1,%2,%3};"
                 : "+f"(d[0]), "+f"(d[1]), "+f"(d[2]), "+f"(d[3])
                 : "r"(a[0]), "r"(a[1]), "r"(a[2]), "r"(a[3]), "r"(b[0]), "r"(b[1]));
}
__device__ __forceinline__ void cp16(uint32_t saddr, const void* gaddr) {
    asm volatile("cp.async.cg.shared.global [%0], [%1], 16;" :: "r"(saddr), "l"(gaddr));
}
__device__ __forceinline__ uint32_t to_tf32(float v) {
    uint32_t r;
    asm("cvt.rna.tf32.f32 %0, %1;" : "=r"(r) : "f"(v));
    return r;
}
__device__ __forceinline__ uint32_t to_tf32u(uint32_t v) {
    uint32_t r;
    asm("cvt.rna.tf32.f32 %0, %1;" : "=r"(r) : "f"(__uint_as_float(v)));
    return r;
}
// streaming stores (evict-first): output has zero reuse; keep it out of L2
__device__ __forceinline__ void stcs2(float* p, float a, float b) {
    asm volatile("st.global.cs.v2.f32 [%0], {%1, %2};" :: "l"(p), "f"(a), "f"(b) : "memory");
}
__device__ __forceinline__ void stcs4z(float* p) {
    asm volatile("st.global.cs.v4.f32 [%0], {%1, %1, %1, %1};" :: "l"(p), "f"(0.f) : "memory");
}

// ---- single kernel: x (65536,25,64), weight (4,64,64) -> out (65536,35,64) ----
// out[n,m,:] = x[n,m+1,:] @ W[deg(m)] ; out[n,24:35,:] = 0
__global__ __launch_bounds__(THREADS, 7)
void dwl_main(const float* __restrict__ x,
              const float* __restrict__ weight,
              float* __restrict__ out)
{
    extern __shared__ float xs[];
    const int t    = threadIdx.x;
    const int lane = t & 31;
    const int cw   = t >> 5;                 // col-warp: cols cw*16..cw*16+15

    const float* xb   = x   + (unsigned)blockIdx.x * (NB * 1600u);
    float*       outb = out + (unsigned)blockIdx.x * (NB * 2240u);

    // zero-fill orders 24..34 (streaming stores)
    for (int i = t; i < NB * 176; i += THREADS) {
        int r = i / 176;
        int j = i - r * 176;
        stcs4z(outb + r * 2240 + 1536 + j * 4);
    }

    const uint32_t xs_b = smem_u32(xs);

    // A-frag ldmatrix addressing (validated R5/R7-R12)
    const uint32_t a_row  = (uint32_t)(lane & 15);
    const uint32_t a_koff = (uint32_t)(lane >> 4) * 16;

    // stage x tile for order m into ring slot b (32 rows x 16 x 16B chunks)
    auto stage = [&](int m, int b) {
        const char* Xg = (const char*)(xb + (m + 1) * 64);
        uint32_t sb = xs_b + (uint32_t)b * (BUFF * 4);
        #pragma unroll
        for (int j = 0; j < 4; j++) {
            int i = t + THREADS * j;
            int r = i >> 4;
            int c = i & 15;
            cp16(sb + (uint32_t)(r * (XS * 4) + c * 16), Xg + r * 6400 + c * 16);
        }
        asm volatile("cp.async.commit_group;" ::: "memory");
    };

    // B fragments straight from weight (LDG, L2-hot) + RN tf32 round.
    // Per 8x8 tile: b0 k = lane&3, b1 k = (lane&3)+4; n = lane>>2.
    uint32_t bh[2][8][2];
    auto load_bfrags = [&](int deg) {
        const float* wb = weight + deg * 4096 + (lane & 3) * 64 + cw * 16 + (lane >> 2);
        #pragma unroll
        for (int nt = 0; nt < 2; nt++)
            #pragma unroll
            for (int ks = 0; ks < 8; ks++) {
                const float* p = wb + ks * 512 + nt * 8;
                bh[nt][ks][0] = to_tf32(p[0]);       // k = ks*8 + (lane&3)
                bh[nt][ks][1] = to_tf32(p[256]);     // k = ks*8 + (lane&3) + 4
            }
    };

    stage(0, 0);
    load_bfrags(0);

    for (int m = 0; m < 24; m++) {
        if (m < 23) {
            stage(m + 1, (m + 1) % 3);
            asm volatile("cp.async.wait_group 1;" ::: "memory");
        } else {
            asm volatile("cp.async.wait_group 0;" ::: "memory");
        }
        __syncthreads();

        if (m == 3)  load_bfrags(1);
        if (m == 8)  load_bfrags(2);
        if (m == 15) load_bfrags(3);

        const uint32_t abase0 = xs_b + (uint32_t)(m % 3) * (BUFF * 4)
                              + a_row * (XS * 4) + a_koff;

        #pragma unroll
        for (int mt = 0; mt < 2; mt++) {
            float acc0[4] = {0.f, 0.f, 0.f, 0.f};
            float acc1[4] = {0.f, 0.f, 0.f, 0.f};
            const uint32_t abase = abase0 + (uint32_t)(mt * 16 * XS * 4);
            #pragma unroll
            for (int ks = 0; ks < 8; ks++) {
                uint32_t a[4];
                ldsm_x4(a, abase + ks * 32);
                #pragma unroll
                for (int j = 0; j < 4; j++) a[j] = to_tf32u(a[j]);  // RN round A
                mma_tf32(acc0, a, bh[0][ks]);
                mma_tf32(acc1, a, bh[1][ks]);
            }
            const int row = mt * 16 + (lane >> 2);
            const int col = m * 64 + cw * 16 + (lane & 3) * 2;
            stcs2(outb + row * 2240 + col,           acc0[0], acc0[1]);
            stcs2(outb + (row + 8) * 2240 + col,     acc0[2], acc0[3]);
            stcs2(outb + row * 2240 + col + 8,       acc1[0], acc1[1]);
            stcs2(outb + (row + 8) * 2240 + col + 8, acc1[2], acc1[3]);
        }
        // ring depth 3: slot written in iter m was last read in iter m-2;
        // the barrier in iter m-1 orders those reads before these writes.
    }
}

extern "C" void kernel_launch(void* const* d_in, const int* in_sizes, int n_in,
                              void* d_out, int out_size)
{
    const float* x = (const float*)d_in[0];
    const float* w = (const float*)d_in[1];
    if (n_in >= 2 && in_sizes[0] < in_sizes[1]) {
        x = (const float*)d_in[1];
        w = (const float*)d_in[0];
    }
    float* out = (float*)d_out;

    const int smem_sz = 3 * BUFF * sizeof(float);   // 26112 B
    cudaFuncSetAttribute(dwl_main, cudaFuncAttributeMaxDynamicSharedMemorySize, smem_sz);
    dwl_main<<<65536 / NB, THREADS, smem_sz>>>(x, w, out);
}

// round 15
// speedup vs baseline: 1.0954x; 1.0010x over previous
#include <cuda_runtime.h>
#include <cstdint>

#define THREADS 128
#define NB 32
#define XS 68                    // smem row stride (floats): 272B, conflict-free LDSM phases
#define BUFF (NB * XS)           // floats per x ring buffer

__device__ __forceinline__ uint32_t smem_u32(const void* p) {
    uint32_t a;
    asm("{ .reg .u64 t; cvta.to.shared.u64 t, %1; cvt.u32.u64 %0, t; }" : "=r"(a) : "l"(p));
    return a;
}
__device__ __forceinline__ void ldsm_x4(uint32_t* r, uint32_t addr) {
    asm volatile("ldmatrix.sync.aligned.m8n8.x4.shared.b16 {%0,%1,%2,%3}, [%4];"
                 : "=r"(r[0]), "=r"(r[1]), "=r"(r[2]), "=r"(r[3]) : "r"(addr));
}
__device__ __forceinline__ void mma_tf32(float* d, const uint32_t* a, const uint32_t* b) {
    asm volatile("mma.sync.aligned.m16n8k8.row.col.f32.tf32.tf32.f32 "
                 "{%0,%1,%2,%3},{%4,%5,%6,%7},{%8,%9},{%0,%1,%2,%3};"
                 : "+f"(d[0]), "+f"(d[1]), "+f"(d[2]), "+f"(d[3])
                 : "r"(a[0]), "r"(a[1]), "r"(a[2]), "r"(a[3]), "r"(b[0]), "r"(b[1]));
}
__device__ __forceinline__ void cp16(uint32_t saddr, const void* gaddr) {
    asm volatile("cp.async.cg.shared.global [%0], [%1], 16;" :: "r"(saddr), "l"(gaddr));
}
__device__ __forceinline__ uint32_t to_tf32(float v) {
    uint32_t r;
    asm("cvt.rna.tf32.f32 %0, %1;" : "=r"(r) : "f"(v));
    return r;
}
// streaming stores (evict-first): output has zero reuse; keep it out of L2
__device__ __forceinline__ void stcs2(float* p, float a, float b) {
    asm volatile("st.global.cs.v2.f32 [%0], {%1, %2};" :: "l"(p), "f"(a), "f"(b) : "memory");
}
__device__ __forceinline__ void stcs4z(float* p) {
    asm volatile("st.global.cs.v4.f32 [%0], {%1, %1, %1, %1};" :: "l"(p), "f"(0.f) : "memory");
}

// ---- single kernel: x (65536,25,64), weight (4,64,64) -> out (65536,35,64) ----
// out[n,m,:] = x[n,m+1,:] @ W[deg(m)] ; out[n,24:35,:] = 0
__global__ __launch_bounds__(THREADS, 7)
void dwl_main(const float* __restrict__ x,
              const float* __restrict__ weight,
              float* __restrict__ out)
{
    extern __shared__ float xs[];
    const int t    = threadIdx.x;
    const int lane = t & 31;
    const int cw   = t >> 5;                 // col-warp: cols cw*16..cw*16+15

    const float* xb   = x   + (unsigned)blockIdx.x * (NB * 1600u);
    float*       outb = out + (unsigned)blockIdx.x * (NB * 2240u);

    const uint32_t xs_b = smem_u32(xs);

    // A-frag ldmatrix addressing (validated R5/R7-R13)
    const uint32_t a_row  = (uint32_t)(lane & 15);
    const uint32_t a_koff = (uint32_t)(lane >> 4) * 16;

    // stage x tile for order m into ring slot b (32 rows x 16 x 16B chunks)
    auto stage = [&](int m, int b) {
        const char* Xg = (const char*)(xb + (m + 1) * 64);
        uint32_t sb = xs_b + (uint32_t)b * (BUFF * 4);
        #pragma unroll
        for (int j = 0; j < 4; j++) {
            int i = t + THREADS * j;
            int r = i >> 4;
            int c = i & 15;
            cp16(sb + (uint32_t)(r * (XS * 4) + c * 16), Xg + r * 6400 + c * 16);
        }
        asm volatile("cp.async.commit_group;" ::: "memory");
    };

    // Kick off tile 0 load FIRST so its DRAM round-trip overlaps the
    // zero-fill stores and B-frag loads below.
    stage(0, 0);

    // zero-fill orders 24..34 (streaming stores)
    for (int i = t; i < NB * 176; i += THREADS) {
        int r = i / 176;
        int j = i - r * 176;
        stcs4z(outb + r * 2240 + 1536 + j * 4);
    }

    // B fragments straight from weight (LDG, L2-hot) + RN tf32 round.
    // Per 8x8 tile: b0 k = lane&3, b1 k = (lane&3)+4; n = lane>>2.
    uint32_t bh[2][8][2];
    auto load_bfrags = [&](int deg) {
        const float* wb = weight + deg * 4096 + (lane & 3) * 64 + cw * 16 + (lane >> 2);
        #pragma unroll
        for (int nt = 0; nt < 2; nt++)
            #pragma unroll
            for (int ks = 0; ks < 8; ks++) {
                const float* p = wb + ks * 512 + nt * 8;
                bh[nt][ks][0] = to_tf32(p[0]);       // k = ks*8 + (lane&3)
                bh[nt][ks][1] = to_tf32(p[256]);     // k = ks*8 + (lane&3) + 4
            }
    };
    load_bfrags(0);

    for (int m = 0; m < 24; m++) {
        if (m < 23) {
            stage(m + 1, (m + 1) % 3);
            asm volatile("cp.async.wait_group 1;" ::: "memory");
        } else {
            asm volatile("cp.async.wait_group 0;" ::: "memory");
        }
        __syncthreads();

        if (m == 3)  load_bfrags(1);
        if (m == 8)  load_bfrags(2);
        if (m == 15) load_bfrags(3);

        const uint32_t abase0 = xs_b + (uint32_t)(m % 3) * (BUFF * 4)
                              + a_row * (XS * 4) + a_koff;

        #pragma unroll
        for (int mt = 0; mt < 2; mt++) {
            float acc0[4] = {0.f, 0.f, 0.f, 0.f};
            float acc1[4] = {0.f, 0.f, 0.f, 0.f};
            const uint32_t abase = abase0 + (uint32_t)(mt * 16 * XS * 4);
            #pragma unroll
            for (int ks = 0; ks < 8; ks++) {
                uint32_t a[4];
                ldsm_x4(a, abase + ks * 32);
                // Round-to-nearest at tf32 precision via half-ulp bit add:
                // MMA datapath reads bits [31:13], so +0x1000 == RN (ties up).
                #pragma unroll
                for (int j = 0; j < 4; j++) a[j] += 0x1000u;
                mma_tf32(acc0, a, bh[0][ks]);
                mma_tf32(acc1, a, bh[1][ks]);
            }
            const int row = mt * 16 + (lane >> 2);
            const int col = m * 64 + cw * 16 + (lane & 3) * 2;
            stcs2(outb + row * 2240 + col,           acc0[0], acc0[1]);
            stcs2(outb + (row + 8) * 2240 + col,     acc0[2], acc0[3]);
            stcs2(outb + row * 2240 + col + 8,       acc1[0], acc1[1]);
            stcs2(outb + (row + 8) * 2240 + col + 8, acc1[2], acc1[3]);
        }
        // ring depth 3: slot written in iter m was last read in iter m-2;
        // the barrier in iter m-1 orders those reads before these writes.
    }
}

extern "C" void kernel_launch(void* const* d_in, const int* in_sizes, int n_in,
                              void* d_out, int out_size)
{
    const float* x = (const float*)d_in[0];
    const float* w = (const float*)d_in[1];
    if (n_in >= 2 && in_sizes[0] < in_sizes[1]) {
        x = (const float*)d_in[1];
        w = (const float*)d_in[0];
    }
    float* out = (float*)d_out;

    const int smem_sz = 3 * BUFF * sizeof(float);   // 26112 B
    cudaFuncSetAttribute(dwl_main, cudaFuncAttributeMaxDynamicSharedMemorySize, smem_sz);
    dwl_main<<<65536 / NB, THREADS, smem_sz>>>(x, w, out);
}

// round 16
// speedup vs baseline: 1.1057x; 1.0094x over previous
#include <cuda_runtime.h>
#include <cstdint>

#define THREADS 128
#define NB 32
#define XS 68                    // smem row stride (floats): 272B, conflict-free LDSM phases
#define BUFF (NB * XS)           // floats per x ring buffer

__device__ __forceinline__ uint32_t smem_u32(const void* p) {
    uint32_t a;
    asm("{ .reg .u64 t; cvta.to.shared.u64 t, %1; cvt.u32.u64 %0, t; }" : "=r"(a) : "l"(p));
    return a;
}
__device__ __forceinline__ void ldsm_x4(uint32_t* r, uint32_t addr) {
    asm volatile("ldmatrix.sync.aligned.m8n8.x4.shared.b16 {%0,%1,%2,%3}, [%4];"
                 : "=r"(r[0]), "=r"(r[1]), "=r"(r[2]), "=r"(r[3]) : "r"(addr));
}
__device__ __forceinline__ void mma_tf32(float* d, const uint32_t* a, const uint32_t* b) {
    asm volatile("mma.sync.aligned.m16n8k8.row.col.f32.tf32.tf32.f32 "
                 "{%0,%1,%2,%3},{%4,%5,%6,%7},{%8,%9},{%0,%1,%2,%3};"
                 : "+f"(d[0]), "+f"(d[1]), "+f"(d[2]), "+f"(d[3])
                 : "r"(a[0]), "r"(a[1]), "r"(a[2]), "r"(a[3]), "r"(b[0]), "r"(b[1]));
}
// cp.async with L2 evict-first cache hint: x is strictly single-use
__device__ __forceinline__ void cp16_ef(uint32_t saddr, const void* gaddr, uint64_t pol) {
    asm volatile("cp.async.cg.shared.global.L2::cache_hint [%0], [%1], 16, %2;"
                 :: "r"(saddr), "l"(gaddr), "l"(pol));
}
__device__ __forceinline__ uint32_t to_tf32(float v) {
    uint32_t r;
    asm("cvt.rna.tf32.f32 %0, %1;" : "=r"(r) : "f"(v));
    return r;
}
// streaming stores (evict-first): output has zero reuse; keep it out of L2
__device__ __forceinline__ void stcs2(float* p, float a, float b) {
    asm volatile("st.global.cs.v2.f32 [%0], {%1, %2};" :: "l"(p), "f"(a), "f"(b) : "memory");
}
__device__ __forceinline__ void stcs4z(float* p) {
    asm volatile("st.global.cs.v4.f32 [%0], {%1, %1, %1, %1};" :: "l"(p), "f"(0.f) : "memory");
}

// ---- single kernel: x (65536,25,64), weight (4,64,64) -> out (65536,35,64) ----
// out[n,m,:] = x[n,m+1,:] @ W[deg(m)] ; out[n,24:35,:] = 0
__global__ __launch_bounds__(THREADS, 7)
void dwl_main(const float* __restrict__ x,
              const float* __restrict__ weight,
              float* __restrict__ out)
{
    extern __shared__ float xs[];
    const int t    = threadIdx.x;
    const int lane = t & 31;
    const int cw   = t >> 5;                 // col-warp: cols cw*16..cw*16+15

    const float* xb   = x   + (unsigned)blockIdx.x * (NB * 1600u);
    float*       outb = out + (unsigned)blockIdx.x * (NB * 2240u);

    const uint32_t xs_b = smem_u32(xs);

    // L2 evict-first access policy for the single-use x stream
    uint64_t pol;
    asm("createpolicy.fractional.L2::evict_first.b64 %0, 1.0;" : "=l"(pol));

    // A-frag ldmatrix addressing (validated R5/R7-R15)
    const uint32_t a_row  = (uint32_t)(lane & 15);
    const uint32_t a_koff = (uint32_t)(lane >> 4) * 16;

    // stage x tile for order m into ring slot b (32 rows x 16 x 16B chunks)
    auto stage = [&](int m, int b) {
        const char* Xg = (const char*)(xb + (m + 1) * 64);
        uint32_t sb = xs_b + (uint32_t)b * (BUFF * 4);
        #pragma unroll
        for (int j = 0; j < 4; j++) {
            int i = t + THREADS * j;
            int r = i >> 4;
            int c = i & 15;
            cp16_ef(sb + (uint32_t)(r * (XS * 4) + c * 16), Xg + r * 6400 + c * 16, pol);
        }
        asm volatile("cp.async.commit_group;" ::: "memory");
    };

    // Kick off tile 0 load FIRST so its DRAM round-trip overlaps the
    // zero-fill stores and B-frag loads below.
    stage(0, 0);

    // zero-fill orders 24..34 (streaming stores)
    for (int i = t; i < NB * 176; i += THREADS) {
        int r = i / 176;
        int j = i - r * 176;
        stcs4z(outb + r * 2240 + 1536 + j * 4);
    }

    // B fragments straight from weight (LDG, L2-hot, default policy: reused) + RN round.
    // Per 8x8 tile: b0 k = lane&3, b1 k = (lane&3)+4; n = lane>>2.
    uint32_t bh[2][8][2];
    auto load_bfrags = [&](int deg) {
        const float* wb = weight + deg * 4096 + (lane & 3) * 64 + cw * 16 + (lane >> 2);
        #pragma unroll
        for (int nt = 0; nt < 2; nt++)
            #pragma unroll
            for (int ks = 0; ks < 8; ks++) {
                const float* p = wb + ks * 512 + nt * 8;
                bh[nt][ks][0] = to_tf32(p[0]);       // k = ks*8 + (lane&3)
                bh[nt][ks][1] = to_tf32(p[256]);     // k = ks*8 + (lane&3) + 4
            }
    };
    load_bfrags(0);

    for (int m = 0; m < 24; m++) {
        if (m < 23) {
            stage(m + 1, (m + 1) % 3);
            asm volatile("cp.async.wait_group 1;" ::: "memory");
        } else {
            asm volatile("cp.async.wait_group 0;" ::: "memory");
        }
        __syncthreads();

        if (m == 3)  load_bfrags(1);
        if (m == 8)  load_bfrags(2);
        if (m == 15) load_bfrags(3);

        const uint32_t abase0 = xs_b + (uint32_t)(m % 3) * (BUFF * 4)
                              + a_row * (XS * 4) + a_koff;

        #pragma unroll
        for (int mt = 0; mt < 2; mt++) {
            float acc0[4] = {0.f, 0.f, 0.f, 0.f};
            float acc1[4] = {0.f, 0.f, 0.f, 0.f};
            const uint32_t abase = abase0 + (uint32_t)(mt * 16 * XS * 4);
            #pragma unroll
            for (int ks = 0; ks < 8; ks++) {
                uint32_t a[4];
                ldsm_x4(a, abase + ks * 32);
                // Round-to-nearest at tf32 precision via half-ulp bit add:
                // MMA datapath reads bits [31:13], so +0x1000 == RN (ties up).
                #pragma unroll
                for (int j = 0; j < 4; j++) a[j] += 0x1000u;
                mma_tf32(acc0, a, bh[0][ks]);
                mma_tf32(acc1, a, bh[1][ks]);
            }
            const int row = mt * 16 + (lane >> 2);
            const int col = m * 64 + cw * 16 + (lane & 3) * 2;
            stcs2(outb + row * 2240 + col,           acc0[0], acc0[1]);
            stcs2(outb + (row + 8) * 2240 + col,     acc0[2], acc0[3]);
            stcs2(outb + row * 2240 + col + 8,       acc1[0], acc1[1]);
            stcs2(outb + (row + 8) * 2240 + col + 8, acc1[2], acc1[3]);
        }
        // ring depth 3: slot written in iter m was last read in iter m-2;
        // the barrier in iter m-1 orders those reads before these writes.
    }
}

extern "C" void kernel_launch(void* const* d_in, const int* in_sizes, int n_in,
                              void* d_out, int out_size)
{
    const float* x = (const float*)d_in[0];
    const float* w = (const float*)d_in[1];
    if (n_in >= 2 && in_sizes[0] < in_sizes[1]) {
        x = (const float*)d_in[1];
        w = (const float*)d_in[0];
    }
    float* out = (float*)d_out;

    const int smem_sz = 3 * BUFF * sizeof(float);   // 26112 B
    cudaFuncSetAttribute(dwl_main, cudaFuncAttributeMaxDynamicSharedMemorySize, smem_sz);
    dwl_main<<<65536 / NB, THREADS, smem_sz>>>(x, w, out);
}

// round 17
// speedup vs baseline: 1.1370x; 1.0283x over previous
#include <cuda_runtime.h>
#include <cstdint>

#define THREADS 128
#define NB 32
#define XS 68                    // smem row stride (floats): 272B, conflict-free LDSM phases
#define BUFF (NB * XS)           // floats per x ring buffer

__device__ __forceinline__ uint32_t smem_u32(const void* p) {
    uint32_t a;
    asm("{ .reg .u64 t; cvta.to.shared.u64 t, %1; cvt.u32.u64 %0, t; }" : "=r"(a) : "l"(p));
    return a;
}
__device__ __forceinline__ void ldsm_x4(uint32_t* r, uint32_t addr) {
    asm volatile("ldmatrix.sync.aligned.m8n8.x4.shared.b16 {%0,%1,%2,%3}, [%4];"
                 : "=r"(r[0]), "=r"(r[1]), "=r"(r[2]), "=r"(r[3]) : "r"(addr));
}
__device__ __forceinline__ void mma_tf32(float* d, const uint32_t* a, const uint32_t* b) {
    asm volatile("mma.sync.aligned.m16n8k8.row.col.f32.tf32.tf32.f32 "
                 "{%0,%1,%2,%3},{%4,%5,%6,%7},{%8,%9},{%0,%1,%2,%3};"
                 : "+f"(d[0]), "+f"(d[1]), "+f"(d[2]), "+f"(d[3])
                 : "r"(a[0]), "r"(a[1]), "r"(a[2]), "r"(a[3]), "r"(b[0]), "r"(b[1]));
}
// cp.async with L2 evict-first cache hint: x is strictly single-use
__device__ __forceinline__ void cp16_ef(uint32_t saddr, const void* gaddr, uint64_t pol) {
    asm volatile("cp.async.cg.shared.global.L2::cache_hint [%0], [%1], 16, %2;"
                 :: "r"(saddr), "l"(gaddr), "l"(pol));
}
__device__ __forceinline__ uint32_t to_tf32(float v) {
    uint32_t r;
    asm("cvt.rna.tf32.f32 %0, %1;" : "=r"(r) : "f"(v));
    return r;
}
// streaming stores (evict-first): output has zero reuse; keep it out of L2
__device__ __forceinline__ void stcs4(float* p, float a, float b, float c, float d) {
    asm volatile("st.global.cs.v4.f32 [%0], {%1, %2, %3, %4};"
                 :: "l"(p), "f"(a), "f"(b), "f"(c), "f"(d) : "memory");
}
__device__ __forceinline__ void stcs4z(float* p) {
    asm volatile("st.global.cs.v4.f32 [%0], {%1, %1, %1, %1};" :: "l"(p), "f"(0.f) : "memory");
}

// ---- single kernel: x (65536,25,64), weight (4,64,64) -> out (65536,35,64) ----
// out[n,m,:] = x[n,m+1,:] @ W[deg(m)] ; out[n,24:35,:] = 0
__global__ __launch_bounds__(THREADS, 7)
void dwl_main(const float* __restrict__ x,
              const float* __restrict__ weight,
              float* __restrict__ out)
{
    extern __shared__ float xs[];
    const int t    = threadIdx.x;
    const int lane = t & 31;
    const int cw   = t >> 5;                 // col-warp: cols cw*16..cw*16+15

    const float* xb   = x   + (unsigned)blockIdx.x * (NB * 1600u);
    float*       outb = out + (unsigned)blockIdx.x * (NB * 2240u);

    const uint32_t xs_b = smem_u32(xs);

    // L2 evict-first access policy for the single-use x stream
    uint64_t pol;
    asm("createpolicy.fractional.L2::evict_first.b64 %0, 1.0;" : "=l"(pol));

    // A-frag ldmatrix addressing (validated R5/R7-R16)
    const uint32_t a_row  = (uint32_t)(lane & 15);
    const uint32_t a_koff = (uint32_t)(lane >> 4) * 16;

    // stage x tile for order m into ring slot b (32 rows x 16 x 16B chunks)
    auto stage = [&](int m, int b) {
        const char* Xg = (const char*)(xb + (m + 1) * 64);
        uint32_t sb = xs_b + (uint32_t)b * (BUFF * 4);
        #pragma unroll
        for (int j = 0; j < 4; j++) {
            int i = t + THREADS * j;
            int r = i >> 4;
            int c = i & 15;
            cp16_ef(sb + (uint32_t)(r * (XS * 4) + c * 16), Xg + r * 6400 + c * 16, pol);
        }
        asm volatile("cp.async.commit_group;" ::: "memory");
    };

    // Kick off tile 0 load FIRST so its DRAM round-trip overlaps the
    // zero-fill stores and B-frag loads below.
    stage(0, 0);

    // zero-fill orders 24..34 (streaming stores)
    for (int i = t; i < NB * 176; i += THREADS) {
        int r = i / 176;
        int j = i - r * 176;
        stcs4z(outb + r * 2240 + 1536 + j * 4);
    }

    // B fragments straight from weight (LDG, L2-hot) + RN tf32 round.
    // n-PERMUTATION for vectorized stores: B-frag n-index u maps to actual col
    //   ntile0: 4*(u>>1) + (u&1)      ntile1: 4*(u>>1) + (u&1) + 2
    // so lane l's D pairs (acc0, acc1) cover actual cols 4q..4q+3 (q = l&3),
    // enabling one STG.128 per row. Pure column relabeling; math unchanged.
    uint32_t bh[2][8][2];
    auto load_bfrags = [&](int deg) {
        const int u  = lane >> 2;
        const int n0 = 4 * (u >> 1) + (u & 1);            // ntile0 actual col offset
        const float* wb = weight + deg * 4096 + (lane & 3) * 64 + cw * 16 + n0;
        #pragma unroll
        for (int nt = 0; nt < 2; nt++)
            #pragma unroll
            for (int ks = 0; ks < 8; ks++) {
                const float* p = wb + ks * 512 + nt * 2;  // ntile1 = +2 cols
                bh[nt][ks][0] = to_tf32(p[0]);            // k = ks*8 + (lane&3)
                bh[nt][ks][1] = to_tf32(p[256]);          // k = ks*8 + (lane&3) + 4
            }
    };
    load_bfrags(0);

    for (int m = 0; m < 24; m++) {
        if (m < 23) {
            stage(m + 1, (m + 1) % 3);
            asm volatile("cp.async.wait_group 1;" ::: "memory");
        } else {
            asm volatile("cp.async.wait_group 0;" ::: "memory");
        }
        __syncthreads();

        if (m == 3)  load_bfrags(1);
        if (m == 8)  load_bfrags(2);
        if (m == 15) load_bfrags(3);

        const uint32_t abase0 = xs_b + (uint32_t)(m % 3) * (BUFF * 4)
                              + a_row * (XS * 4) + a_koff;

        #pragma unroll
        for (int mt = 0; mt < 2; mt++) {
            float acc0[4] = {0.f, 0.f, 0.f, 0.f};
            float acc1[4] = {0.f, 0.f, 0.f, 0.f};
            const uint32_t abase = abase0 + (uint32_t)(mt * 16 * XS * 4);
            #pragma unroll
            for (int ks = 0; ks < 8; ks++) {
                uint32_t a[4];
                ldsm_x4(a, abase + ks * 32);
                // Round-to-nearest at tf32 precision via half-ulp bit add:
                // MMA datapath reads bits [31:13], so +0x1000 == RN (ties up).
                #pragma unroll
                for (int j = 0; j < 4; j++) a[j] += 0x1000u;
                mma_tf32(acc0, a, bh[0][ks]);
                mma_tf32(acc1, a, bh[1][ks]);
            }
            // lane holds actual cols 4q..4q+3 (q = lane&3) after n-permutation
            const int row = mt * 16 + (lane >> 2);
            const int col = m * 64 + cw * 16 + (lane & 3) * 4;
            stcs4(outb + row * 2240 + col,
                  acc0[0], acc0[1], acc1[0], acc1[1]);
            stcs4(outb + (row + 8) * 2240 + col,
                  acc0[2], acc0[3], acc1[2], acc1[3]);
        }
        // ring depth 3: slot written in iter m was last read in iter m-2;
        // the barrier in iter m-1 orders those reads before these writes.
    }
}

extern "C" void kernel_launch(void* const* d_in, const int* in_sizes, int n_in,
                              void* d_out, int out_size)
{
    const float* x = (const float*)d_in[0];
    const float* w = (const float*)d_in[1];
    if (n_in >= 2 && in_sizes[0] < in_sizes[1]) {
        x = (const float*)d_in[1];
        w = (const float*)d_in[0];
    }
    float* out = (float*)d_out;

    const int smem_sz = 3 * BUFF * sizeof(float);   // 26112 B
    cudaFuncSetAttribute(dwl_main, cudaFuncAttributeMaxDynamicSharedMemorySize, smem_sz);
    dwl_main<<<65536 / NB, THREADS, smem_sz>>>(x, w, out);
}